// round 13
// baseline (speedup 1.0000x reference)
#include <cuda_runtime.h>
#include <cuda_fp16.h>
#include <cstdint>

#define N_OUT   11008
#define K_IN    4096
#define M_TOK   32
#define NTILES  1376      // 8-channel output tiles
#define CNT     5         // tiles per CTA
#define GRID    276       // ceil(1376/5): single wave at occ 2

#define RING_OFF   65536  // ring starts after 64KB x-staging region
#define STAGE_BYTES 16384 // one (kc,nt) weight stage for all 8 warps
#define SMEM_TOTAL (RING_OFF + 3 * STAGE_BYTES)   // 112 KB

// Pre-converted x image, staging order: [(w*4+r)*512 + row*16 + b*8 + u] 16B units
__device__ uint4 g_xh[16384];   // 256 KB

__device__ __forceinline__ void mma16816(float c[4],
                                         unsigned a0, unsigned a1, unsigned a2, unsigned a3,
                                         unsigned b0, unsigned b1) {
    asm volatile(
        "mma.sync.aligned.m16n8k16.row.col.f32.f16.f16.f32 "
        "{%0,%1,%2,%3}, {%4,%5,%6,%7}, {%8,%9}, {%0,%1,%2,%3};\n"
        : "+f"(c[0]), "+f"(c[1]), "+f"(c[2]), "+f"(c[3])
        : "r"(a0), "r"(a1), "r"(a2), "r"(a3), "r"(b0), "r"(b1));
}

// Pack byte0 of four int32s (low byte == int8 bits)
__device__ __forceinline__ unsigned pack4(int4 v) {
    unsigned t0 = __byte_perm((unsigned)v.x, (unsigned)v.y, 0x0040);
    unsigned t1 = __byte_perm((unsigned)v.z, (unsigned)v.w, 0x0040);
    return __byte_perm(t0, t1, 0x5410);
}

__device__ __forceinline__ void cp16(uint32_t dst, const void* src) {
    asm volatile("cp.async.cg.shared.global [%0], [%1], 16;"
                 :: "r"(dst), "l"(src) : "memory");
}
__device__ __forceinline__ void cp_commit() {
    asm volatile("cp.async.commit_group;" ::: "memory");
}
__device__ __forceinline__ void cp_wait2() {
    asm volatile("cp.async.wait_group 2;" ::: "memory");
}

// Issue one weight stage (64B per lane as 4 x 16B cp.async) into ring slot.
__device__ __forceinline__ void issue_stage(uint32_t ring_wl, int slot,
                                            const int* __restrict__ gp) {
    uint32_t d = ring_wl + slot * STAGE_BYTES;
    cp16(d,        gp);
    cp16(d + 512,  gp + 4);
    cp16(d + 1024, gp + 8);
    cp16(d + 1536, gp + 12);
    cp_commit();
}

// ---- Pre-kernel: x fp32 -> fp16, staging-ordered image ----
__global__ void x_prep(const float* __restrict__ x) {
    int t = blockIdx.x * 256 + threadIdx.x;            // 0..16383
    int w = t >> 11, r = (t >> 9) & 3, lin = t & 511;
    int row = lin >> 4, bu = lin & 15;
    int k = w * 512 + r * 128 + bu * 8;
    const float* src = x + (size_t)row * K_IN + k;
    float4 f0 = *reinterpret_cast<const float4*>(src);
    float4 f1 = *reinterpret_cast<const float4*>(src + 4);
    __half2 h0 = __floats2half2_rn(f0.x, f0.y);
    __half2 h1 = __floats2half2_rn(f0.z, f0.w);
    __half2 h2 = __floats2half2_rn(f1.x, f1.y);
    __half2 h3 = __floats2half2_rn(f1.z, f1.w);
    uint4 v;
    v.x = *reinterpret_cast<unsigned*>(&h0);
    v.y = *reinterpret_cast<unsigned*>(&h1);
    v.z = *reinterpret_cast<unsigned*>(&h2);
    v.w = *reinterpret_cast<unsigned*>(&h3);
    g_xh[t] = v;
}

// ---- Main fused kernel: single wave, warps split K 8-way, cp.async weight
// ring (depth 3, issue-ahead 2), fused smem reduction + epilogue ----
// k-permutation (audited): thread (g=lane/4, tg=lane%4) owns logical
// k = tg*16 + {0..15} per k64 chunk; mma step s uses logical k tg*16+4s+{0,1} at
// hw slots {2tg,2tg+1} and +{2,3} at {2tg+8,2tg+9}; A from smem uses same map.
__global__ void __launch_bounds__(256, 2)
qlinear_fused(const int* __restrict__ qw, const float* __restrict__ scales,
              const float* __restrict__ bias, float* __restrict__ out) {
    extern __shared__ __align__(16) unsigned char smem[];
    const int t = threadIdx.x, w = t >> 5, lane = t & 31;
    const int g = lane >> 2, tg = lane & 3;
    const int tile0 = blockIdx.x * CNT;

    // Lean addressing: one base pointer + small element-offsets per nt.
    const int tb0 = (tile0 < NTILES) ? tile0 : (NTILES - 1);
    const int* wb0 = qw + (size_t)(tb0 * 8 + g) * K_IN + w * 512 + tg * 16;
    int off[CNT];
#pragma unroll
    for (int nt = 0; nt < CNT; nt++) {
        int tile = tile0 + nt; if (tile > NTILES - 1) tile = NTILES - 1;
        off[nt] = (tile - tb0) * (8 * K_IN);
    }

    const uint32_t smem_u32 = (uint32_t)__cvta_generic_to_shared(smem);
    const uint32_t ring_wl  = smem_u32 + RING_OFF + w * 2048 + lane * 16;
    const unsigned char* ring_rd = smem + RING_OFF + w * 2048 + lane * 16;

    float c[CNT][2][4];
#pragma unroll
    for (int nt = 0; nt < CNT; nt++)
#pragma unroll
        for (int mh = 0; mh < 2; mh++)
#pragma unroll
            for (int q = 0; q < 4; q++) c[nt][mh][q] = 0.f;

    const __half2 magic = __halves2half2(__ushort_as_half(0x6480), __ushort_as_half(0x6480));

    // Prologue: issue stages 0 (r0,kc0,nt0) and 1 (r0,kc0,nt1)
    issue_stage(ring_wl, 0, wb0 + off[0]);
    issue_stage(ring_wl, 1, wb0 + off[1]);
    int slot = 2, cslot = 0;

#pragma unroll 1
    for (int r = 0; r < 4; r++) {
        __syncwarp();
        // Stage this warp's 8KB x region for round r (32 tok x 128 k, fp16)
        const uint4* src = g_xh + (w * 4 + r) * 512;
        unsigned char* dst = smem + w * 8192;
#pragma unroll
        for (int i = 0; i < 16; i++) {
            int lin = i * 32 + lane;
            int row = lin >> 4, b = (lin >> 3) & 1, u = lin & 7;
            uint4 v = src[lin];
            *reinterpret_cast<uint4*>(dst + row * 256 + b * 128 + ((u ^ (row & 7)) << 4)) = v;
        }
        __syncwarp();

#pragma unroll
        for (int kc = 0; kc < 2; kc++) {
            // A fragments: rows g+8rr, 16 halves each, swizzled
            unsigned A[4][8];
#pragma unroll
            for (int rr = 0; rr < 4; rr++) {
                const unsigned char* base = dst + (g + 8 * rr) * 256 + kc * 128;
                uint4 lo = *reinterpret_cast<const uint4*>(base + (((tg * 2 + 0) ^ g) << 4));
                uint4 hi = *reinterpret_cast<const uint4*>(base + (((tg * 2 + 1) ^ g) << 4));
                A[rr][0] = lo.x; A[rr][1] = lo.y; A[rr][2] = lo.z; A[rr][3] = lo.w;
                A[rr][4] = hi.x; A[rr][5] = hi.y; A[rr][6] = hi.z; A[rr][7] = hi.w;
            }
#pragma unroll
            for (int nt = 0; nt < CNT; nt++) {
                // Issue stage j+2 (j = r*10 + kc*5 + nt); clamp past the end.
                {
                    const int q = kc * 5 + nt + 2;        // compile-time 2..11
                    const int* gp;
                    if (q < 10) {
                        gp = wb0 + off[q % 5] + r * 128 + (q / 5) * 64;
                    } else if (r < 3) {
                        gp = wb0 + off[q - 10] + (r + 1) * 128;
                    } else {
                        gp = wb0 + off[4] + 3 * 128 + 64; // clamp to last stage
                    }
                    issue_stage(ring_wl, slot, gp);
                    slot = (slot == 2) ? 0 : slot + 1;
                }
                cp_wait2();   // stage j is complete

                // Consume stage j from ring (per-lane data: no barrier needed)
                const int4* rp = reinterpret_cast<const int4*>(ring_rd + cslot * STAGE_BYTES);
                int4 w0 = rp[0], w1 = rp[32], w2 = rp[64], w3 = rp[96];
                cslot = (cslot == 2) ? 0 : cslot + 1;
                unsigned ps[4];
                ps[0] = pack4(w0); ps[1] = pack4(w1); ps[2] = pack4(w2); ps[3] = pack4(w3);

#pragma unroll
                for (int s = 0; s < 4; s++) {
                    unsigned ts = ps[s] ^ 0x80808080u;
                    unsigned lo = __byte_perm(ts, 0x64646464u, 0x4140);
                    unsigned hi = __byte_perm(ts, 0x64646464u, 0x4342);
                    __half2 b0h = __hsub2(*reinterpret_cast<__half2*>(&lo), magic);
                    __half2 b1h = __hsub2(*reinterpret_cast<__half2*>(&hi), magic);
                    unsigned b0 = *reinterpret_cast<unsigned*>(&b0h);
                    unsigned b1 = *reinterpret_cast<unsigned*>(&b1h);
                    mma16816(c[nt][0], A[0][2*s], A[1][2*s], A[0][2*s+1], A[1][2*s+1], b0, b1);
                    mma16816(c[nt][1], A[2][2*s], A[3][2*s], A[2][2*s+1], A[3][2*s+1], b0, b1);
                }
            }
        }
    }

    // Drain any clamped over-issued groups before smem reuse.
    asm volatile("cp.async.wait_group 0;" ::: "memory");

    // ---- Intra-CTA reduction over the 8 k-slice warps + fused epilogue ----
    __syncthreads();
    float* red = reinterpret_cast<float*>(smem);   // [nt][tok][ch][w'] = 40KB
#pragma unroll
    for (int nt = 0; nt < CNT; nt++)
#pragma unroll
        for (int mh = 0; mh < 2; mh++)
#pragma unroll
            for (int q = 0; q < 4; q++) {
                int tok = mh * 16 + g + ((q >> 1) << 3);
                int ch  = tg * 2 + (q & 1);
                red[(nt * 256 + tok * 8 + ch) * 8 + ((w + tok) & 7)] = c[nt][mh][q];
            }
    __syncthreads();

#pragma unroll
    for (int i = 0; i < CNT; i++) {
        int e = t + i * 256;                        // 0..1279
        int nt = e >> 8, rem = e & 255, tok = rem >> 3, ch = rem & 7;
        int tile = tile0 + nt;
        if (tile < NTILES) {
            const float* p = red + e * 8;
            float4 a = *reinterpret_cast<const float4*>(p);
            float4 b = *reinterpret_cast<const float4*>(p + 4);
            float s = ((a.x + a.y) + (a.z + a.w)) + ((b.x + b.y) + (b.z + b.w));
            int n = tile * 8 + ch;
            out[(size_t)tok * N_OUT + n] = s * scales[n] + bias[n];
        }
    }
}

extern "C" void kernel_launch(void* const* d_in, const int* in_sizes, int n_in,
                              void* d_out, int out_size) {
    const float* x      = (const float*)d_in[0];
    const int*   qw     = (const int*)d_in[1];
    const float* scales = (const float*)d_in[2];
    const float* bias   = (const float*)d_in[3];
    float*       out    = (float*)d_out;

    cudaFuncSetAttribute((const void*)qlinear_fused,
                         cudaFuncAttributeMaxDynamicSharedMemorySize, SMEM_TOTAL);
    x_prep<<<64, 256>>>(x);
    qlinear_fused<<<GRID, 256, SMEM_TOTAL>>>(qw, scales, bias, out);
}

// round 14
// speedup vs baseline: 1.7216x; 1.7216x over previous
#include <cuda_runtime.h>
#include <cuda_fp16.h>
#include <cstdint>

#define N_OUT   11008
#define K_IN    4096
#define M_TOK   32
#define NTILES  1376      // 8-channel output tiles
#define TPC     6         // tiles per CTA (2 n-groups x 3)
#define CNT     3         // tiles per n-group
#define GRID    230       // ceil(1376/6): single wave at occ 2

// Pre-converted x image: [(ks*8 + r)*512 + row*16 + bu] 16B units
__device__ uint4 g_xh[16384];   // 256 KB

__device__ __forceinline__ void mma16816(float c[4],
                                         unsigned a0, unsigned a1, unsigned a2, unsigned a3,
                                         unsigned b0, unsigned b1) {
    asm volatile(
        "mma.sync.aligned.m16n8k16.row.col.f32.f16.f16.f32 "
        "{%0,%1,%2,%3}, {%4,%5,%6,%7}, {%8,%9}, {%0,%1,%2,%3};\n"
        : "+f"(c[0]), "+f"(c[1]), "+f"(c[2]), "+f"(c[3])
        : "r"(a0), "r"(a1), "r"(a2), "r"(a3), "r"(b0), "r"(b1));
}

// Pack byte0 of four int32s (low byte == int8 bits)
__device__ __forceinline__ unsigned pack4(int4 v) {
    unsigned t0 = __byte_perm((unsigned)v.x, (unsigned)v.y, 0x0040);
    unsigned t1 = __byte_perm((unsigned)v.z, (unsigned)v.w, 0x0040);
    return __byte_perm(t0, t1, 0x5410);
}

__device__ __forceinline__ void loadW(int4 W[4], const int* __restrict__ p) {
#pragma unroll
    for (int s = 0; s < 4; s++) W[s] = *reinterpret_cast<const int4*>(p + s * 4);
}

// ---- Pre-kernel: x fp32 -> fp16, staging-ordered image ----
// unit t: ks=t>>12, r=(t>>9)&7, lin=t&511; row=lin>>4, bu=lin&15
// holds halves for token=row, k = ks*1024 + r*128 + bu*8 + {0..7}
__global__ void x_prep(const float* __restrict__ x) {
    int t = blockIdx.x * 256 + threadIdx.x;            // 0..16383
    int ks = t >> 12, r = (t >> 9) & 7, lin = t & 511;
    int row = lin >> 4, bu = lin & 15;
    int k = ks * 1024 + r * 128 + bu * 8;
    const float* src = x + (size_t)row * K_IN + k;
    float4 f0 = *reinterpret_cast<const float4*>(src);
    float4 f1 = *reinterpret_cast<const float4*>(src + 4);
    __half2 h0 = __floats2half2_rn(f0.x, f0.y);
    __half2 h1 = __floats2half2_rn(f0.z, f0.w);
    __half2 h2 = __floats2half2_rn(f1.x, f1.y);
    __half2 h3 = __floats2half2_rn(f1.z, f1.w);
    uint4 v;
    v.x = *reinterpret_cast<unsigned*>(&h0);
    v.y = *reinterpret_cast<unsigned*>(&h1);
    v.z = *reinterpret_cast<unsigned*>(&h2);
    v.w = *reinterpret_cast<unsigned*>(&h3);
    g_xh[t] = v;
}

// ---- Main fused kernel: single wave; 2 n-groups x 4 k-slices per CTA;
// 2-ahead register weight prefetch; fused smem reduction + epilogue ----
// k-permutation (audited): thread (g=lane/4, tg=lane%4) owns logical
// k = tg*16 + {0..15} per k64 chunk; mma step s uses logical k tg*16+4s+{0,1} at
// hw slots {2tg,2tg+1} and +{2,3} at {2tg+8,2tg+9}; A from smem uses same map.
__global__ void __launch_bounds__(256, 2)
qlinear_fused(const int* __restrict__ qw, const float* __restrict__ scales,
              const float* __restrict__ bias, float* __restrict__ out) {
    extern __shared__ __align__(16) unsigned char smem[];
    const int t = threadIdx.x, w = t >> 5, lane = t & 31;
    const int g = lane >> 2, tg = lane & 3;
    const int ng = w >> 2, ks = w & 3;
    const int grp0 = blockIdx.x * TPC + ng * CNT;

    // Lean addressing: one clamped base pointer + small element-offsets per nt.
    const int tb0 = (grp0 < NTILES) ? grp0 : (NTILES - 1);
    const int* wb0 = qw + (size_t)(tb0 * 8 + g) * K_IN + ks * 1024 + tg * 16;
    int off[CNT];
#pragma unroll
    for (int nt = 0; nt < CNT; nt++) {
        int tile = grp0 + nt; if (tile > NTILES - 1) tile = NTILES - 1;
        off[nt] = (tile - tb0) * (8 * K_IN);           // element offset, fits int32
    }

    float c[CNT][2][4];
#pragma unroll
    for (int nt = 0; nt < CNT; nt++)
#pragma unroll
        for (int mh = 0; mh < 2; mh++)
#pragma unroll
            for (int q = 0; q < 4; q++) c[nt][mh][q] = 0.f;

    const __half2 magic = __halves2half2(__ushort_as_half(0x6480), __ushort_as_half(0x6480));

    // 2-ahead double-buffered weight prefetch.
    // Stage j = (r*2 + kc)*3 + nt. Buffer parity pc = (kc*3+nt)&1 (6 stages/round:
    // parity pattern repeats each round; j and j+2 share parity).
    int4 W[2][4];
    loadW(W[0], wb0 + off[0]);            // stage (0,0,0)
    loadW(W[1], wb0 + off[1]);            // stage (0,0,1)

#pragma unroll 1
    for (int r = 0; r < 8; r++) {
        __syncwarp();
        // Stage this warp's 8KB x region for round r (32 tok x 128 k, fp16)
        const uint4* src = g_xh + (ks * 8 + r) * 512;
        unsigned char* dst = smem + w * 8192;
#pragma unroll
        for (int i = 0; i < 16; i++) {
            int lin = i * 32 + lane;
            int row = lin >> 4, b = (lin >> 3) & 1, u = lin & 7;
            uint4 v = src[lin];
            *reinterpret_cast<uint4*>(dst + row * 256 + b * 128 + ((u ^ (row & 7)) << 4)) = v;
        }
        __syncwarp();

#pragma unroll
        for (int kc = 0; kc < 2; kc++) {
            // A fragments: rows g+8rr, 16 halves each, swizzled
            unsigned A[4][8];
#pragma unroll
            for (int rr = 0; rr < 4; rr++) {
                const unsigned char* base = dst + (g + 8 * rr) * 256 + kc * 128;
                uint4 lo = *reinterpret_cast<const uint4*>(base + (((tg * 2 + 0) ^ g) << 4));
                uint4 hi = *reinterpret_cast<const uint4*>(base + (((tg * 2 + 1) ^ g) << 4));
                A[rr][0] = lo.x; A[rr][1] = lo.y; A[rr][2] = lo.z; A[rr][3] = lo.w;
                A[rr][4] = hi.x; A[rr][5] = hi.y; A[rr][6] = hi.z; A[rr][7] = hi.w;
            }
#pragma unroll
            for (int nt = 0; nt < CNT; nt++) {
                const int pc = (kc * 3 + nt) & 1;
                // Consume stage j: pack early, freeing W[pc] for the j+2 issue.
                unsigned ps[4];
#pragma unroll
                for (int s = 0; s < 4; s++) ps[s] = pack4(W[pc][s]);

                // Issue stage j+2 into W[pc] (same parity). Clamp at the end.
                {
                    const int q = kc * 3 + nt + 2;     // compile-time 2..7
                    const int* gp;
                    if (q < 6)        gp = wb0 + off[q % 3] + r * 128 + (q / 3) * 64;
                    else if (r < 7)   gp = wb0 + off[q - 6] + (r + 1) * 128;
                    else              gp = wb0 + off[2] + 7 * 128 + 64;  // clamp
                    loadW(W[pc], gp);
                }

#pragma unroll
                for (int s = 0; s < 4; s++) {
                    unsigned ts = ps[s] ^ 0x80808080u;
                    unsigned lo = __byte_perm(ts, 0x64646464u, 0x4140);
                    unsigned hi = __byte_perm(ts, 0x64646464u, 0x4342);
                    __half2 b0h = __hsub2(*reinterpret_cast<__half2*>(&lo), magic);
                    __half2 b1h = __hsub2(*reinterpret_cast<__half2*>(&hi), magic);
                    unsigned b0 = *reinterpret_cast<unsigned*>(&b0h);
                    unsigned b1 = *reinterpret_cast<unsigned*>(&b1h);
                    mma16816(c[nt][0], A[0][2*s], A[1][2*s], A[0][2*s+1], A[1][2*s+1], b0, b1);
                    mma16816(c[nt][1], A[2][2*s], A[3][2*s], A[2][2*s+1], A[3][2*s+1], b0, b1);
                }
            }
        }
    }

    // ---- Intra-CTA reduction over 4 k-slices per n-group + fused epilogue ----
    __syncthreads();
    float* red = reinterpret_cast<float*>(smem);   // [grp][tok][ch][ks'] = 24KB
#pragma unroll
    for (int nt = 0; nt < CNT; nt++)
#pragma unroll
        for (int mh = 0; mh < 2; mh++)
#pragma unroll
            for (int q = 0; q < 4; q++) {
                int tok = mh * 16 + g + ((q >> 1) << 3);
                int ch  = tg * 2 + (q & 1);
                int grp = ng * CNT + nt;
                red[((grp * 256 + tok * 8 + ch) << 2) + ((ks + tok) & 3)] = c[nt][mh][q];
            }
    __syncthreads();

#pragma unroll
    for (int i = 0; i < TPC; i++) {
        int e = t + i * 256;                        // 0..1535
        int grp = e >> 8, rem = e & 255, tok = rem >> 3, ch = rem & 7;
        int tile = blockIdx.x * TPC + grp;
        if (tile < NTILES) {
            float4 a = *reinterpret_cast<const float4*>(red + (e << 2));
            float s = (a.x + a.y) + (a.z + a.w);
            int n = tile * 8 + ch;
            out[(size_t)tok * N_OUT + n] = s * scales[n] + bias[n];
        }
    }
}

extern "C" void kernel_launch(void* const* d_in, const int* in_sizes, int n_in,
                              void* d_out, int out_size) {
    const float* x      = (const float*)d_in[0];
    const int*   qw     = (const int*)d_in[1];
    const float* scales = (const float*)d_in[2];
    const float* bias   = (const float*)d_in[3];
    float*       out    = (float*)d_out;

    cudaFuncSetAttribute((const void*)qlinear_fused,
                         cudaFuncAttributeMaxDynamicSharedMemorySize, 65536);
    x_prep<<<64, 256>>>(x);
    qlinear_fused<<<GRID, 256, 65536>>>(qw, scales, bias, out);
}